// round 2
// baseline (speedup 1.0000x reference)
#include <cuda_runtime.h>
#include <cuda_bf16.h>
#include <cstddef>

// Problem constants (fixed by the dataset): N=4, HW=4096, C=64.
#define HW   4096
#define CDIM 64
#define SCALE 0.125f   // 1/sqrt(64)

// Scratch: E[n][q][k] = exp(scale * Q[n,q,:].K[n,k,:])   (256 MiB)
__device__ float g_E[(size_t)4 * HW * HW];
// denom[n][k] = sum_q E[n][q][k]
__device__ float g_denom[4 * HW];

__global__ void zero_denom_kernel() {
    int i = blockIdx.x * blockDim.x + threadIdx.x;
    if (i < 4 * HW) g_denom[i] = 0.0f;
}

// Phase A: 64x64 tile of E = exp(scale * Q Kt), plus column sums (over q) into g_denom.
// grid: (HW/64 k-tiles, HW/64 q-tiles, N), block: 256 (16x16, each thread 4q x 4k)
__global__ void __launch_bounds__(256) phaseA_kernel(const float* __restrict__ Q,
                                                     const float* __restrict__ K) {
    const int n  = blockIdx.z;
    const int q0 = blockIdx.y * 64;
    const int k0 = blockIdx.x * 64;
    const float* Qb = Q + ((size_t)n * HW + q0) * CDIM;
    const float* Kb = K + ((size_t)n * HW + k0) * CDIM;

    __shared__ float Qs[64][68];  // [c][q]  (transposed on load)
    __shared__ float Ks[64][68];  // [c][k]
    __shared__ float red[64];     // per-block column sums

    const int tid = threadIdx.x;
    if (tid < 64) red[tid] = 0.0f;

    // Load both 64x64 tiles (1024 float4 each), transpose into smem.
#pragma unroll
    for (int i = 0; i < 4; i++) {
        int lin = tid + i * 256;          // 0..1023
        int row = lin >> 4;               // local row (q or k)
        int c4  = (lin & 15) * 4;         // c offset
        float4 v = *(const float4*)(Qb + row * CDIM + c4);
        Qs[c4 + 0][row] = v.x; Qs[c4 + 1][row] = v.y;
        Qs[c4 + 2][row] = v.z; Qs[c4 + 3][row] = v.w;
        float4 w = *(const float4*)(Kb + row * CDIM + c4);
        Ks[c4 + 0][row] = w.x; Ks[c4 + 1][row] = w.y;
        Ks[c4 + 2][row] = w.z; Ks[c4 + 3][row] = w.w;
    }
    __syncthreads();

    const int tx = tid & 15;   // k micro-tile
    const int ty = tid >> 4;   // q micro-tile

    float acc[4][4] = {};
#pragma unroll 16
    for (int c = 0; c < 64; c++) {
        float4 qv = *(const float4*)&Qs[c][ty * 4];
        float4 kv = *(const float4*)&Ks[c][tx * 4];
        float qa[4] = {qv.x, qv.y, qv.z, qv.w};
        float ka[4] = {kv.x, kv.y, kv.z, kv.w};
#pragma unroll
        for (int i = 0; i < 4; i++)
#pragma unroll
            for (int j = 0; j < 4; j++)
                acc[i][j] += qa[i] * ka[j];
    }

    // exp, store E ([n][q][k], k contiguous), accumulate column sums over q.
    float csum[4] = {0.f, 0.f, 0.f, 0.f};
#pragma unroll
    for (int i = 0; i < 4; i++) {
        float e0 = __expf(acc[i][0] * SCALE);
        float e1 = __expf(acc[i][1] * SCALE);
        float e2 = __expf(acc[i][2] * SCALE);
        float e3 = __expf(acc[i][3] * SCALE);
        size_t off = ((size_t)n * HW + (q0 + ty * 4 + i)) * HW + (k0 + tx * 4);
        *(float4*)(g_E + off) = make_float4(e0, e1, e2, e3);
        csum[0] += e0; csum[1] += e1; csum[2] += e2; csum[3] += e3;
    }
#pragma unroll
    for (int j = 0; j < 4; j++)
        atomicAdd(&red[tx * 4 + j], csum[j]);
    __syncthreads();

    if (tid < 64)
        atomicAdd(&g_denom[n * HW + k0 + tid], red[tid]);
}

// Phase B: Out[n,q,c] = sum_k E[n,q,k] * V[n,k,c] / denom[n,k]
// grid: (HW/64 q-tiles, 1, N), block 256 (16x16, each thread 4q x 4c), k-loop inside.
__global__ void __launch_bounds__(256) phaseB_kernel(const float* __restrict__ V,
                                                     float* __restrict__ Out) {
    const int n  = blockIdx.z;
    const int q0 = blockIdx.x * 64;

    __shared__ float Es[64][68];  // [k][q] (transposed on load)
    __shared__ float Vs[64][68];  // [k][c] (pre-scaled by 1/denom)

    const int tid = threadIdx.x;
    const int tx = tid & 15;   // c micro-tile
    const int ty = tid >> 4;   // q micro-tile

    float acc[4][4] = {};

    for (int k0 = 0; k0 < HW; k0 += 64) {
#pragma unroll
        for (int i = 0; i < 4; i++) {
            int lin = tid + i * 256;
            int row = lin >> 4;           // q local (for E) / k local (for V)
            int c4  = (lin & 15) * 4;     // k local (for E) / c (for V)
            float4 v = *(const float4*)(g_E + ((size_t)n * HW + q0 + row) * HW + k0 + c4);
            Es[c4 + 0][row] = v.x; Es[c4 + 1][row] = v.y;
            Es[c4 + 2][row] = v.z; Es[c4 + 3][row] = v.w;

            float dinv = __frcp_rn(g_denom[n * HW + k0 + row]);
            float4 w = *(const float4*)(V + ((size_t)n * HW + k0 + row) * CDIM + c4);
            Vs[row][c4 + 0] = w.x * dinv; Vs[row][c4 + 1] = w.y * dinv;
            Vs[row][c4 + 2] = w.z * dinv; Vs[row][c4 + 3] = w.w * dinv;
        }
        __syncthreads();

#pragma unroll 16
        for (int kk = 0; kk < 64; kk++) {
            float4 ev = *(const float4*)&Es[kk][ty * 4];
            float4 vv = *(const float4*)&Vs[kk][tx * 4];
            float ea[4] = {ev.x, ev.y, ev.z, ev.w};
            float va[4] = {vv.x, vv.y, vv.z, vv.w};
#pragma unroll
            for (int i = 0; i < 4; i++)
#pragma unroll
                for (int j = 0; j < 4; j++)
                    acc[i][j] += ea[i] * va[j];
        }
        __syncthreads();
    }

#pragma unroll
    for (int i = 0; i < 4; i++) {
        size_t off = ((size_t)n * HW + (q0 + ty * 4 + i)) * CDIM + tx * 4;
        *(float4*)(Out + off) = make_float4(acc[i][0], acc[i][1], acc[i][2], acc[i][3]);
    }
}

extern "C" void kernel_launch(void* const* d_in, const int* in_sizes, int n_in,
                              void* d_out, int out_size) {
    const float* Q = (const float*)d_in[0];
    const float* K = (const float*)d_in[1];
    const float* V = (const float*)d_in[2];
    float* Out = (float*)d_out;

    const int N = in_sizes[0] / (HW * CDIM);  // = 4

    zero_denom_kernel<<<(4 * HW + 255) / 256, 256>>>();
    phaseA_kernel<<<dim3(HW / 64, HW / 64, N), 256>>>(Q, K);
    phaseB_kernel<<<dim3(HW / 64, 1, N), 256>>>(V, Out);
}